// round 17
// baseline (speedup 1.0000x reference)
#include <cuda_runtime.h>
#include <cuda_fp16.h>
#include <math.h>

#define B_   16
#define H_   128
#define W_   128
#define CIN1 256
#define COUT 128

// Scratch (device globals; no allocation).
// xh: [b][chunk32 (8)][h][w*16+ci2]  (2048 words per (b,c,h))
// uph/dnh: [b][chunk32 (4)][h][w*16+ci2]
__device__ unsigned g_xh [(size_t)B_ * 8 * H_ * 2048];
__device__ unsigned g_uph[(size_t)B_ * 4 * H_ * 2048];
__device__ unsigned g_dnh[(size_t)B_ * 4 * H_ * 2048];
// packed A: [chunk32][tap][co][ci2(16)]
__device__ unsigned g_whu[8 * 9 * 2048];
__device__ unsigned g_whd[8 * 9 * 2048];
__device__ unsigned g_whp[4 * 9 * 2048];

struct BNP { const float *g, *b, *m, *v; };

// ---------------- helpers ----------------
__device__ __forceinline__ void cpa16(unsigned dst, const unsigned* src, bool ok) {
    int sz = ok ? 16 : 0;
    asm volatile("cp.async.ca.shared.global [%0], [%1], 16, %2;" :: "r"(dst), "l"(src), "r"(sz));
}
#define CPCOMMIT() asm volatile("cp.async.commit_group;")
#define CPWAIT(n)  asm volatile("cp.async.wait_group %0;"::"n"(n))

__device__ __forceinline__ void mma_f16(float* c, const unsigned* a, unsigned b0, unsigned b1) {
    asm volatile(
        "mma.sync.aligned.m16n8k16.row.col.f32.f16.f16.f32 "
        "{%0,%1,%2,%3},{%4,%5,%6,%7},{%8,%9},{%0,%1,%2,%3};"
        : "+f"(c[0]), "+f"(c[1]), "+f"(c[2]), "+f"(c[3])
        : "r"(a[0]), "r"(a[1]), "r"(a[2]), "r"(a[3]), "r"(b0), "r"(b1));
}
__device__ __forceinline__ void ldsm4(unsigned* r, unsigned addr) {
    asm volatile("ldmatrix.sync.aligned.m8n8.x4.shared.b16 {%0,%1,%2,%3}, [%4];"
                 : "=r"(r[0]), "=r"(r[1]), "=r"(r[2]), "=r"(r[3]) : "r"(addr));
}
__device__ __forceinline__ unsigned h2u(float lo, float hi) {
    __half2 h = __floats2half2_rn(lo, hi);
    return *(unsigned*)&h;
}
__device__ __forceinline__ unsigned smem_u32(const void* p) {
    unsigned a;
    asm("{ .reg .u64 t; cvta.to.shared.u64 t, %1; cvt.u32.u64 %0, t; }" : "=r"(a) : "l"(p));
    return a;
}

// 64B rows; swizzle: kq' = kq ^ ((row>>1)&3)  (conflict-free 8-quad permutation)
// smem bytes per buffer: ws 9*128*64 = 73728, xs 4 rows * 132px * 64 = 33792
#define WS_B 73728
#define XS_B 33792
#define BUF_B (WS_B + XS_B)                  // 107520
#define SMEM_BYTES (2 * BUF_B + 64)          // + alignment slack
#define XROW_B 8448                          // 132*64 bytes per xs h-row

// ---------------------------------------------------------------------------
// fp16 mma.sync implicit-GEMM 3x3 conv + BN (+ReLU), chunk-32, 2-deep ring,
// ldmatrix.x4 from 64B-row swizzled smem.
// Block=256, tile M=128co x 256px (2 rows x 128w), K streamed 32ci/chunk.
// OUT=0: emit chunk-32 interleaved half2 tensor. OUT=1: fused LeftPool -> fp32 NCHW.
// gridDim.z=2 selects (w0,p0,o0)/(w1,p1,o1) (merged conv1+conv2).
// ---------------------------------------------------------------------------
template <int NCC, bool RELU, int OUT>
__global__ __launch_bounds__(256, 1)
void conv_h(const unsigned* __restrict__ xh,
            const unsigned* __restrict__ w0p, const unsigned* __restrict__ w1p,
            BNP p0, BNP p1,
            unsigned* __restrict__ o0, unsigned* __restrict__ o1)
{
    extern __shared__ unsigned sm[];
    const unsigned smb0 = smem_u32(sm);
    const unsigned pad  = (64u - (smb0 & 63u)) & 63u;
    const unsigned smb  = smb0 + pad;
    char* smc = (char*)sm + pad;

    const int tid  = threadIdx.x;
    const int b    = blockIdx.y;
    const int h0   = blockIdx.x * 2;
    const int z    = blockIdx.z;

    const unsigned* wh = z ? w1p : w0p;
    const BNP       pp = z ? p1 : p0;
    unsigned*     outv = z ? o1 : o0;

    const int warp = tid >> 5;
    const int lane = tid & 31;
    const int g    = lane >> 2;
    const int tig  = lane & 3;

    const int mwarp  = warp & 1;
    const int nwarp  = warp >> 1;
    const int rloc   = nwarp >> 1;
    const int wn0    = (nwarp & 1) * 64;
    const int cobase = mwarp * 64;

    // ---- per-lane ldmatrix byte offsets (ks step -> XOR 32) ----
    unsigned aoff[4];
#pragma unroll
    for (int mt = 0; mt < 4; mt++) {
        int arow = cobase + mt * 16 + (lane & 15);
        aoff[mt] = arow * 64 + ((((unsigned)(lane >> 4)) ^ ((arow >> 1) & 3)) << 4);
    }
    const int bl = (lane & 7) + ((lane >> 4) << 3);
    unsigned boff[4][3];
#pragma unroll
    for (int ntp = 0; ntp < 4; ntp++)
#pragma unroll
        for (int dw = 0; dw < 3; dw++) {
            int px = wn0 + ntp * 16 + bl + dw;
            boff[ntp][dw] = px * 64 + ((((unsigned)((lane >> 3) & 1)) ^ ((px >> 1) & 3)) << 4);
        }

    // ---- static-zero halo px {0,129,130,131} x 4 kq: 2 bufs x 4 rows x 16 units ----
    if (tid < 128) {
        int buf = tid >> 6, rem = tid & 63, r = rem >> 4, ui = rem & 15;
        int pxsel = ui >> 2, kq = ui & 3;
        int px = (pxsel == 0) ? 0 : (128 + pxsel);
        unsigned byte = buf * BUF_B + WS_B + r * XROW_B + px * 64
                      + ((kq ^ ((px >> 1) & 3)) << 4);
        *(uint4*)(smc + byte) = make_uint4(0, 0, 0, 0);
    }

    float acc[4][8][4];
#pragma unroll
    for (int mt = 0; mt < 4; mt++)
#pragma unroll
        for (int nt = 0; nt < 8; nt++)
#pragma unroll
            for (int i = 0; i < 4; i++) acc[mt][nt][i] = 0.f;

    auto stage = [&](int c) {
        unsigned wsd = smb + (c & 1) * BUF_B;
        unsigned xsd = wsd + WS_B;
        const unsigned* wsrc = wh + (size_t)c * 18432;
        // weights: 9 taps x 128 co x 4 kq = 4608 16B units
#pragma unroll
        for (int k = 0; k < 18; k++) {
            int fi = tid + (k << 8);
            int tap = fi >> 9, rem = fi & 511, co = rem >> 2, kq = rem & 3;
            cpa16(wsd + tap * 8192 + co * 64 + ((kq ^ ((co >> 1) & 3)) << 4),
                  wsrc + fi * 4, true);
        }
        // x: 4 h-rows x 512 units (128 w x 4 kq); dest px = w+1
#pragma unroll
        for (int k = 0; k < 8; k++) {
            int fi = tid + (k << 8);
            int r = fi >> 9, j = fi & 511;
            int gh = h0 - 1 + r;
            bool ok = (gh >= 0) && (gh < H_);
            int px = (j >> 2) + 1, kq = j & 3;
            cpa16(xsd + r * XROW_B + px * 64 + ((kq ^ ((px >> 1) & 3)) << 4),
                  xh + ((size_t)(b * NCC + c) * H_ + (ok ? gh : 0)) * 2048 + j * 4, ok);
        }
    };

    stage(0); CPCOMMIT();

    for (int c = 0; c < NCC; c++) {
        CPWAIT(0);
        __syncthreads();   // stage(c) visible; all warps done with compute(c-1)
        if (c + 1 < NCC) { stage(c + 1); CPCOMMIT(); }   // buf (c+1)&1 == (c-1)&1, free

        const unsigned wsb_ = smb + (c & 1) * BUF_B;
        const unsigned xsb_ = wsb_ + WS_B;

#pragma unroll
        for (int dh = 0; dh < 3; dh++) {
            const unsigned xrow = xsb_ + (rloc + dh) * XROW_B;
#pragma unroll
            for (int dw = 0; dw < 3; dw++) {
                const unsigned wtap = wsb_ + (dh * 3 + dw) * 8192;
#pragma unroll
                for (int ks = 0; ks < 2; ks++) {
                    unsigned a[4][4];
#pragma unroll
                    for (int mt = 0; mt < 4; mt++)
                        ldsm4(a[mt], (wtap + aoff[mt]) ^ (ks << 5));
#pragma unroll
                    for (int ntp = 0; ntp < 4; ntp++) {
                        unsigned bb[4];
                        ldsm4(bb, (xrow + boff[ntp][dw]) ^ (ks << 5));
#pragma unroll
                        for (int mt = 0; mt < 4; mt++) {
                            mma_f16(acc[mt][2 * ntp],     a[mt], bb[0], bb[1]);
                            mma_f16(acc[mt][2 * ntp + 1], a[mt], bb[2], bb[3]);
                        }
                    }
                }
            }
        }
    }

    // ---- epilogue: BN (+ReLU) ----
    const int h = h0 + rloc;
    if (OUT == 0) {
#pragma unroll
        for (int mt = 0; mt < 4; mt++) {
            int ca = cobase + mt * 16 + g;     // pair lo
            int cb2 = ca + 8;                  // pair hi
            float inva = pp.g[ca]  * rsqrtf(pp.v[ca]  + 1e-5f);
            float bia  = pp.b[ca]  - pp.m[ca]  * inva;
            float invb = pp.g[cb2] * rsqrtf(pp.v[cb2] + 1e-5f);
            float bib  = pp.b[cb2] - pp.m[cb2] * invb;
            // pair row j = mwarp*32 + mt*8 + g  ->  c32 = j>>4, s = j&15
            int c32 = mwarp * 2 + (mt >> 1);
            int s   = (mt & 1) * 8 + g;
            unsigned* rp = outv + ((size_t)(b * 4 + c32) * H_ + h) * 2048 + s;
#pragma unroll
            for (int nt = 0; nt < 8; nt++) {
                int w0 = wn0 + nt * 8 + 2 * tig;
                float v0 = acc[mt][nt][0] * inva + bia;
                float v1 = acc[mt][nt][1] * inva + bia;
                float v2 = acc[mt][nt][2] * invb + bib;
                float v3 = acc[mt][nt][3] * invb + bib;
                if (RELU) { v0=fmaxf(v0,0.f); v1=fmaxf(v1,0.f); v2=fmaxf(v2,0.f); v3=fmaxf(v3,0.f); }
                rp[w0 * 16]      = h2u(v0, v2);
                rp[w0 * 16 + 16] = h2u(v1, v3);
            }
        }
    } else {
        // ---- fused LeftPool: BN -> smem -> reverse cummax over W -> fp32 NCHW ----
        float* sc = (float*)smc;              // [256 rows (co*2+r)][pitch 132]
        __syncthreads();                      // mainloop smem reads complete everywhere
#pragma unroll
        for (int mt = 0; mt < 4; mt++) {
            int ca = cobase + mt * 16 + g;
            int cb2 = ca + 8;
            float inva = pp.g[ca]  * rsqrtf(pp.v[ca]  + 1e-5f);
            float bia  = pp.b[ca]  - pp.m[ca]  * inva;
            float invb = pp.g[cb2] * rsqrtf(pp.v[cb2] + 1e-5f);
            float bib  = pp.b[cb2] - pp.m[cb2] * invb;
            float* r0 = sc + (ca * 2 + rloc) * 132;
            float* r1 = sc + (cb2 * 2 + rloc) * 132;
#pragma unroll
            for (int nt = 0; nt < 8; nt++) {
                int w0 = wn0 + nt * 8 + 2 * tig;
                *(float2*)(r0 + w0) = make_float2(acc[mt][nt][0] * inva + bia,
                                                  acc[mt][nt][1] * inva + bia);
                *(float2*)(r1 + w0) = make_float2(acc[mt][nt][2] * invb + bib,
                                                  acc[mt][nt][3] * invb + bib);
            }
        }
        __syncthreads();
        // float4 reverse max-scan of one (co,r) row per thread (short RAW chain)
        {
            float4* rw4 = (float4*)(sc + tid * 132);   // 528B-aligned
            float run = -INFINITY;
#pragma unroll 4
            for (int w4 = 31; w4 >= 0; w4--) {
                float4 f = rw4[w4];
                f.w = fmaxf(run, f.w);
                f.z = fmaxf(f.w, f.z);
                f.y = fmaxf(f.z, f.y);
                f.x = fmaxf(f.y, f.x);
                run = f.x;
                rw4[w4] = f;
            }
        }
        __syncthreads();
        float* outf = (float*)outv;
#pragma unroll
        for (int k = 0; k < 32; k++) {
            int idx4 = tid + (k << 8);        // 8192 float4s
            int co = idx4 >> 6;
            int r  = (idx4 >> 5) & 1;
            int w4 = idx4 & 31;
            float4 q = *(float4*)(sc + (co * 2 + r) * 132 + w4 * 4);
            ((float4*)(outf + (((size_t)b * COUT + co) * H_ + h0 + r) * W_))[w4] = q;
        }
    }
}

// ---------------------------------------------------------------------------
// Merged prep: xpose (smem transpose per (b,c32,h)) + all weight packs.
// ---------------------------------------------------------------------------
#define XP_BLKS 16384          // B * 8 chunks * H
#define WP1_BLKS 576           // 8*9*2048 words / 256
#define WP3_BLKS 288           // 4*9*2048 words / 256

__device__ __forceinline__ void wpack_body(int idx, int CIN, bool PAIR8,
                                           const float* __restrict__ w,
                                           unsigned* __restrict__ wo)
{
    // idx = ((c*9+tap)*128 + co)*16 + s
    int s   = idx & 15;
    int co  = (idx >> 4) & 127;
    int tap = (idx >> 11) % 9;
    int c   = idx / (9 * 2048);
    int ca, cbb;
    if (PAIR8) { int j = c * 16 + s; ca = 16 * (j >> 3) + (j & 7); cbb = ca + 8; }
    else       { ca = c * 32 + 2 * s; cbb = ca + 1; }
    float wa = w[((size_t)co * CIN + ca)  * 9 + tap];
    float wb = w[((size_t)co * CIN + cbb) * 9 + tap];
    wo[idx] = h2u(wa, wb);
}

__global__ void prep_all(const float* __restrict__ x, unsigned* __restrict__ xh,
                         const float* __restrict__ w_up,   unsigned* __restrict__ whu,
                         const float* __restrict__ w_down, unsigned* __restrict__ whd,
                         const float* __restrict__ w_p,    unsigned* __restrict__ whp)
{
    __shared__ float sx[32 * 130];
    int blk = blockIdx.x;
    int tid = threadIdx.x;
    if (blk < XP_BLKS) {
        int h  = blk & 127;
        int bc = blk >> 7;          // b*8 + c32
#pragma unroll
        for (int k = 0; k < 16; k++) {
            int e = tid + (k << 8);             // 0..4095
            int cil = e >> 7, w = e & 127;
            sx[cil * 130 + w] =
                x[(((size_t)(bc >> 3) * CIN1 + (bc & 7) * 32 + cil) * H_ + h) * W_ + w];
        }
        __syncthreads();
#pragma unroll
        for (int k = 0; k < 8; k++) {
            int o = tid + (k << 8);             // w*16 + s
            int s = o & 15, w = o >> 4;
            xh[((size_t)bc * H_ + h) * 2048 + o] =
                h2u(sx[(2 * s) * 130 + w], sx[(2 * s + 1) * 130 + w]);
        }
    } else if (blk < XP_BLKS + WP1_BLKS) {
        wpack_body((blk - XP_BLKS) * 256 + tid, CIN1, false, w_up, whu);
    } else if (blk < XP_BLKS + 2 * WP1_BLKS) {
        wpack_body((blk - XP_BLKS - WP1_BLKS) * 256 + tid, CIN1, false, w_down, whd);
    } else {
        wpack_body((blk - XP_BLKS - 2 * WP1_BLKS) * 256 + tid, COUT, true, w_p, whp);
    }
}

// ---------------------------------------------------------------------------
// TopPool (reverse cummax over H) + add on chunk-32 interleaved half2 tensors.
// ---------------------------------------------------------------------------
__global__ void tpool_h(const uint2* __restrict__ up, const uint2* __restrict__ dn,
                        uint2* __restrict__ mg)
{
    int idx = blockIdx.x * 256 + threadIdx.x;   // 16*4*1024 = 65536
    int q  = idx & 1023;
    int bc = idx >> 10;
    size_t base = (size_t)bc * H_ * 1024 + q;
    unsigned ru = 0xFC00FC00u;                  // half2(-inf,-inf)
    __half2 run0 = *(__half2*)&ru;
    __half2 run1 = run0;
#pragma unroll 4
    for (int h = H_ - 1; h >= 0; h--) {
        size_t o = base + (size_t)h * 1024;
        uint2 u = up[o];
        uint2 d = dn[o];
        run0 = __hmax2(run0, *(__half2*)&u.x);
        run1 = __hmax2(run1, *(__half2*)&u.y);
        __half2 m0 = __hadd2(run0, *(__half2*)&d.x);
        __half2 m1 = __hadd2(run1, *(__half2*)&d.y);
        uint2 qq; qq.x = *(unsigned*)&m0; qq.y = *(unsigned*)&m1;
        mg[o] = qq;
    }
}

// ---------------------------------------------------------------------------
extern "C" void kernel_launch(void* const* d_in, const int* in_sizes, int n_in,
                              void* d_out, int out_size)
{
    const float* x      = (const float*)d_in[0];
    const float* w_up   = (const float*)d_in[1];
    const float* up_g   = (const float*)d_in[2];
    const float* up_b   = (const float*)d_in[3];
    const float* up_m   = (const float*)d_in[4];
    const float* up_v   = (const float*)d_in[5];
    const float* w_down = (const float*)d_in[6];
    const float* dn_g   = (const float*)d_in[7];
    const float* dn_b   = (const float*)d_in[8];
    const float* dn_m   = (const float*)d_in[9];
    const float* dn_v   = (const float*)d_in[10];
    const float* w_p    = (const float*)d_in[11];
    const float* p_g    = (const float*)d_in[12];
    const float* p_b    = (const float*)d_in[13];
    const float* p_m    = (const float*)d_in[14];
    const float* p_v    = (const float*)d_in[15];
    float* outp = (float*)d_out;

    unsigned *xh, *uph, *dnh, *whu, *whd, *whp;
    cudaGetSymbolAddress((void**)&xh,  g_xh);
    cudaGetSymbolAddress((void**)&uph, g_uph);
    cudaGetSymbolAddress((void**)&dnh, g_dnh);
    cudaGetSymbolAddress((void**)&whu, g_whu);
    cudaGetSymbolAddress((void**)&whd, g_whd);
    cudaGetSymbolAddress((void**)&whp, g_whp);

    cudaFuncSetAttribute(conv_h<8, true,  0>, cudaFuncAttributeMaxDynamicSharedMemorySize, SMEM_BYTES);
    cudaFuncSetAttribute(conv_h<4, false, 1>, cudaFuncAttributeMaxDynamicSharedMemorySize, SMEM_BYTES);

    // prep (single kernel: xpose + all weight packs)
    prep_all<<<XP_BLKS + 2 * WP1_BLKS + WP3_BLKS, 256>>>(
        x, xh, w_up, whu, w_down, whd, w_p, whp);

    BNP pup = { up_g, up_b, up_m, up_v };
    BNP pdn = { dn_g, dn_b, dn_m, dn_v };
    BNP ppp = { p_g,  p_b,  p_m,  p_v  };

    // conv1 + conv2 merged (z selects weight/BN/output set)
    dim3 g12(H_ / 2, B_, 2);
    conv_h<8, true, 0><<<g12, 256, SMEM_BYTES>>>(xh, whu, whd, pup, pdn, uph, dnh);
    // merge = toppool(up) + down
    tpool_h<<<65536 / 256, 256>>>((const uint2*)uph, (const uint2*)dnh, (uint2*)dnh);
    // conv3 + BN + fused LeftPool -> fp32 output
    dim3 g3(H_ / 2, B_, 1);
    conv_h<4, false, 1><<<g3, 256, SMEM_BYTES>>>(dnh, whp, whp, ppp, ppp,
                                                 (unsigned*)outp, (unsigned*)outp);
}